// round 1
// baseline (speedup 1.0000x reference)
#include <cuda_runtime.h>
#include <cstdint>

#define E_DIM 1024
#define H_NUM 16
#define HD 64
#define S_MAX 2048
#define LEVELS 4

// ---------------- scratch (static device globals; no allocs allowed) --------
__device__ float g_qkv[S_MAX * 3 * E_DIM];                 // per-level QKV
__device__ float g_attn[S_MAX * E_DIM];                    // attention output
__device__ float g_outs[(2048 + 1024 + 512 + 256) * E_DIM];// per-level MHA outs
__device__ float g_ups[S_MAX * E_DIM];                     // upsampled current
__device__ float g_cur[1024 * E_DIM];                      // combine intermediate

// ---------------- GEMM: Y[M,N] = X[M,K(ldx)] * W[N,K]^T + bias (+addend) ----
#define BM 64
#define BN 64
#define BK 16

__global__ void __launch_bounds__(256) gemm_bias_kernel(
    const float* __restrict__ X, int ldx,
    const float* __restrict__ W,        // [N,K] row-major
    const float* __restrict__ bias,     // [N]
    const float* __restrict__ addend,   // [M,N] or nullptr
    float* __restrict__ Y,              // [M,N]
    int M, int N, int K)
{
    __shared__ float As[BK][BM];
    __shared__ float Bs[BK][BN];

    const int bm = blockIdx.y * BM;
    const int bn = blockIdx.x * BN;
    const int tid = threadIdx.x;
    const int tx = tid & 15;
    const int ty = tid >> 4;

    const int lr = tid >> 2;        // 0..63
    const int lc = (tid & 3) * 4;   // 0,4,8,12

    float acc[4][4];
#pragma unroll
    for (int i = 0; i < 4; i++)
#pragma unroll
        for (int j = 0; j < 4; j++) acc[i][j] = 0.f;

    const float* Xp = X + (size_t)bm * ldx;
    const float* Wp = W + (size_t)bn * K;

    for (int k0 = 0; k0 < K; k0 += BK) {
        float4 av = *reinterpret_cast<const float4*>(Xp + (size_t)lr * ldx + k0 + lc);
        float4 bv = *reinterpret_cast<const float4*>(Wp + (size_t)lr * K + k0 + lc);
        As[lc + 0][lr] = av.x; As[lc + 1][lr] = av.y;
        As[lc + 2][lr] = av.z; As[lc + 3][lr] = av.w;
        Bs[lc + 0][lr] = bv.x; Bs[lc + 1][lr] = bv.y;
        Bs[lc + 2][lr] = bv.z; Bs[lc + 3][lr] = bv.w;
        __syncthreads();
#pragma unroll
        for (int kk = 0; kk < BK; kk++) {
            float4 a = *reinterpret_cast<const float4*>(&As[kk][ty * 4]);
            float4 b = *reinterpret_cast<const float4*>(&Bs[kk][tx * 4]);
            float ar[4] = {a.x, a.y, a.z, a.w};
            float br[4] = {b.x, b.y, b.z, b.w};
#pragma unroll
            for (int i = 0; i < 4; i++)
#pragma unroll
                for (int j = 0; j < 4; j++) acc[i][j] += ar[i] * br[j];
        }
        __syncthreads();
    }

#pragma unroll
    for (int i = 0; i < 4; i++) {
        const int row = bm + ty * 4 + i;
#pragma unroll
        for (int j = 0; j < 4; j++) {
            const int col = bn + tx * 4 + j;
            float v = acc[i][j] + bias[col];
            if (addend) v += addend[(size_t)row * N + col];
            Y[(size_t)row * N + col] = v;
        }
    }
}

// ---------------- Flash attention, fp32, one (head, 64-query block) per CTA -
// qkv: [L, 3*E]; out: [L, E]
__global__ void __launch_bounds__(256) attn_kernel(
    const float* __restrict__ qkv,
    float* __restrict__ out,
    int L)
{
    extern __shared__ float sm[];
    float* Qs = sm;                 // [d][r]  64x64, pre-scaled
    float* Ks = sm + 64 * 64;       // [d][c]  64x64
    float* Vs = sm + 2 * 64 * 64;   // [c][d]  64x64
    float* Ps = sm + 3 * 64 * 64;   // [c][r]  64x64

    const int h = blockIdx.y;
    const int q0 = blockIdx.x * 64;
    const int tid = threadIdx.x;
    const int tx = tid & 15;
    const int ty = tid >> 4;
    const float scale = 0.125f;     // 1/sqrt(64)

    // load Q tile (scaled), transposed to [d][r]
#pragma unroll
    for (int it = 0; it < 4; it++) {
        int idx = tid + it * 256;           // 0..1023
        int r = idx >> 4;
        int d = (idx & 15) * 4;
        float4 v = *reinterpret_cast<const float4*>(
            qkv + (size_t)(q0 + r) * 3072 + h * 64 + d);
        Qs[(d + 0) * 64 + r] = v.x * scale;
        Qs[(d + 1) * 64 + r] = v.y * scale;
        Qs[(d + 2) * 64 + r] = v.z * scale;
        Qs[(d + 3) * 64 + r] = v.w * scale;
    }

    float m_i[4], l_i[4], accO[4][4];
#pragma unroll
    for (int i = 0; i < 4; i++) {
        m_i[i] = -1e30f; l_i[i] = 0.f;
#pragma unroll
        for (int j = 0; j < 4; j++) accO[i][j] = 0.f;
    }
    __syncthreads();

    for (int kb = 0; kb < L; kb += 64) {
        // load K (transposed [d][c]) and V (natural [c][d])
#pragma unroll
        for (int it = 0; it < 4; it++) {
            int idx = tid + it * 256;
            int c = idx >> 4;
            int d = (idx & 15) * 4;
            const float* base = qkv + (size_t)(kb + c) * 3072 + h * 64 + d;
            float4 kv = *reinterpret_cast<const float4*>(base + 1024);
            Ks[(d + 0) * 64 + c] = kv.x;
            Ks[(d + 1) * 64 + c] = kv.y;
            Ks[(d + 2) * 64 + c] = kv.z;
            Ks[(d + 3) * 64 + c] = kv.w;
            float4 vv = *reinterpret_cast<const float4*>(base + 2048);
            *reinterpret_cast<float4*>(&Vs[c * 64 + d]) = vv;
        }
        __syncthreads();

        // S = (Q*scale) @ K^T  -> s[i][j] for rows ty*4+i, cols tx*4+j
        float s[4][4];
#pragma unroll
        for (int i = 0; i < 4; i++)
#pragma unroll
            for (int j = 0; j < 4; j++) s[i][j] = 0.f;
#pragma unroll 8
        for (int d = 0; d < 64; d++) {
            float4 a = *reinterpret_cast<const float4*>(&Qs[d * 64 + ty * 4]);
            float4 b = *reinterpret_cast<const float4*>(&Ks[d * 64 + tx * 4]);
            float ar[4] = {a.x, a.y, a.z, a.w};
            float br[4] = {b.x, b.y, b.z, b.w};
#pragma unroll
            for (int i = 0; i < 4; i++)
#pragma unroll
                for (int j = 0; j < 4; j++) s[i][j] += ar[i] * br[j];
        }

        // online softmax per row; reduction across the 16-lane tx group
#pragma unroll
        for (int i = 0; i < 4; i++) {
            float mloc = fmaxf(fmaxf(s[i][0], s[i][1]), fmaxf(s[i][2], s[i][3]));
#pragma unroll
            for (int off = 8; off; off >>= 1)
                mloc = fmaxf(mloc, __shfl_xor_sync(0xffffffffu, mloc, off));
            float mnew = fmaxf(m_i[i], mloc);
            float alpha = __expf(m_i[i] - mnew);
            float p[4], lloc = 0.f;
#pragma unroll
            for (int j = 0; j < 4; j++) { p[j] = __expf(s[i][j] - mnew); lloc += p[j]; }
#pragma unroll
            for (int off = 8; off; off >>= 1)
                lloc += __shfl_xor_sync(0xffffffffu, lloc, off);
            l_i[i] = l_i[i] * alpha + lloc;
            m_i[i] = mnew;
#pragma unroll
            for (int j = 0; j < 4; j++) {
                accO[i][j] *= alpha;
                Ps[(tx * 4 + j) * 64 + ty * 4 + i] = p[j];  // store P as [c][r]
            }
        }
        __syncthreads();

        // O += P @ V : inner over keys c
#pragma unroll 8
        for (int c = 0; c < 64; c++) {
            float4 a = *reinterpret_cast<const float4*>(&Ps[c * 64 + ty * 4]);
            float4 b = *reinterpret_cast<const float4*>(&Vs[c * 64 + tx * 4]);
            float ar[4] = {a.x, a.y, a.z, a.w};
            float br[4] = {b.x, b.y, b.z, b.w};
#pragma unroll
            for (int i = 0; i < 4; i++)
#pragma unroll
                for (int j = 0; j < 4; j++) accO[i][j] += ar[i] * br[j];
        }
        __syncthreads();
    }

    // normalize + write (out row q0+r, col h*64 + d)
#pragma unroll
    for (int i = 0; i < 4; i++) {
        float inv = 1.0f / l_i[i];
        const size_t row = (size_t)(q0 + ty * 4 + i);
#pragma unroll
        for (int j = 0; j < 4; j++)
            out[row * E_DIM + h * 64 + tx * 4 + j] = accO[i][j] * inv;
    }
}

// ---------------- linear upsample along sequence ---------------------------
__global__ void __launch_bounds__(256) upsample_kernel(
    const float* __restrict__ x, float* __restrict__ y, int Lsrc, int Ltar)
{
    const int i = blockIdx.x;
    float src = (i + 0.5f) * ((float)Lsrc / (float)Ltar) - 0.5f;
    src = fminf(fmaxf(src, 0.f), (float)(Lsrc - 1));
    int i0 = (int)floorf(src);
    int i1 = min(i0 + 1, Lsrc - 1);
    float w = src - (float)i0;
    const float* a = x + (size_t)i0 * E_DIM;
    const float* b = x + (size_t)i1 * E_DIM;
    float* yp = y + (size_t)i * E_DIM;
    for (int c = threadIdx.x * 4; c < E_DIM; c += blockDim.x * 4) {
        float4 va = *reinterpret_cast<const float4*>(a + c);
        float4 vb = *reinterpret_cast<const float4*>(b + c);
        float4 r;
        r.x = va.x * (1.f - w) + vb.x * w;
        r.y = va.y * (1.f - w) + vb.y * w;
        r.z = va.z * (1.f - w) + vb.z * w;
        r.w = va.w * (1.f - w) + vb.w * w;
        *reinterpret_cast<float4*>(yp + c) = r;
    }
}

// ---------------- launcher --------------------------------------------------
extern "C" void kernel_launch(void* const* d_in, const int* in_sizes, int n_in,
                              void* d_out, int out_size)
{
    const float* query = (const float*)d_in[0];
    const float* in_w  = (const float*)d_in[1];   // [4, 3072, 1024]
    const float* in_b  = (const float*)d_in[2];   // [4, 3072]
    const float* out_w = (const float*)d_in[3];   // [4, 1024, 1024]
    const float* out_b = (const float*)d_in[4];   // [4, 1024]
    const float* up_w  = (const float*)d_in[5];   // [3, 1024, 1024]
    const float* up_b  = (const float*)d_in[6];   // [3, 1024]
    float* out = (float*)d_out;

    cudaFuncSetAttribute(attn_kernel,
                         cudaFuncAttributeMaxDynamicSharedMemorySize, 64 * 1024);

    float *qkv, *attn, *outs, *ups, *cur;
    cudaGetSymbolAddress((void**)&qkv,  g_qkv);
    cudaGetSymbolAddress((void**)&attn, g_attn);
    cudaGetSymbolAddress((void**)&outs, g_outs);
    cudaGetSymbolAddress((void**)&ups,  g_ups);
    cudaGetSymbolAddress((void**)&cur,  g_cur);

    // per-level row offsets into g_outs
    const size_t off[LEVELS] = {0, 2048u * E_DIM, 3072u * E_DIM, 3584u * E_DIM};

    for (int lvl = 0; lvl < LEVELS; lvl++) {
        const int L = S_MAX >> lvl;
        const int stride = 1 << lvl;

        // QKV projection: [L,1024] x [3072,1024]^T  (strided read of query)
        gemm_bias_kernel<<<dim3(3072 / BN, L / BM), 256>>>(
            query, stride * E_DIM,
            in_w + (size_t)lvl * 3072 * E_DIM,
            in_b + (size_t)lvl * 3072,
            nullptr, qkv, L, 3072, E_DIM);

        // attention
        attn_kernel<<<dim3(L / 64, H_NUM), 256, 64 * 1024>>>(qkv, attn, L);

        // out projection -> g_outs[lvl]
        gemm_bias_kernel<<<dim3(E_DIM / BN, L / BM), 256>>>(
            attn, E_DIM,
            out_w + (size_t)lvl * E_DIM * E_DIM,
            out_b + (size_t)lvl * E_DIM,
            nullptr, outs + off[lvl], L, E_DIM, E_DIM);
    }

    // top-down combine
    const float* curp = outs + off[3];
    int Lc = 256;
    for (int lvl = LEVELS - 2; lvl >= 0; lvl--) {
        const int Lf = S_MAX >> lvl;
        upsample_kernel<<<Lf, 256>>>(curp, ups, Lc, Lf);
        float* dst = (lvl == 0) ? out : cur;
        gemm_bias_kernel<<<dim3(E_DIM / BN, Lf / BM), 256>>>(
            ups, E_DIM,
            up_w + (size_t)lvl * E_DIM * E_DIM,
            up_b + (size_t)lvl * E_DIM,
            outs + off[lvl],           // + fine (residual) fused in epilogue
            dst, Lf, E_DIM, E_DIM);
        curp = dst;
        Lc = Lf;
    }
}

// round 2
// speedup vs baseline: 3.0738x; 3.0738x over previous
#include <cuda_runtime.h>
#include <cstdint>

#define E_DIM 1024
#define S_MAX 2048
#define LEVELS 4

// ---------------- scratch ---------------------------------------------------
__device__ float g_qkv[S_MAX * 3 * E_DIM];
__device__ float g_attn[S_MAX * E_DIM];
__device__ float g_outs[(2048 + 1024 + 512 + 256) * E_DIM];
__device__ float g_ups[S_MAX * E_DIM];
__device__ float g_cur[1024 * E_DIM];

// ---------------- helpers ---------------------------------------------------
__device__ __forceinline__ uint32_t f2tf32(float f) {
    uint32_t r;
    asm("cvt.rna.tf32.f32 %0, %1;" : "=r"(r) : "f"(f));
    return r;
}

__device__ __forceinline__ void mma_tf32(float* c, const uint32_t* a,
                                         uint32_t b0, uint32_t b1) {
    asm volatile(
        "mma.sync.aligned.m16n8k8.row.col.f32.tf32.tf32.f32 "
        "{%0,%1,%2,%3}, {%4,%5,%6,%7}, {%8,%9}, {%0,%1,%2,%3};"
        : "+f"(c[0]), "+f"(c[1]), "+f"(c[2]), "+f"(c[3])
        : "r"(a[0]), "r"(a[1]), "r"(a[2]), "r"(a[3]), "r"(b0), "r"(b1));
}

// ---------------- tensor-core GEMM: Y = X[M,K(ldx)] @ W[N,K]^T + bias (+add)
#define BM 128
#define BN 128
#define BK 32
#define SST 36   // smem row stride (floats): bank = (4r + c) % 32 -> conflict-free frags

__global__ void __launch_bounds__(256) gemm_tc(
    const float* __restrict__ X, int ldx,
    const float* __restrict__ W,
    const float* __restrict__ bias,
    const float* __restrict__ addend,
    float* __restrict__ Y,
    int M, int N, int K)
{
    extern __shared__ uint32_t smem[];
    uint32_t* As = smem;                 // [2][BM][SST]
    uint32_t* Bs = smem + 2 * BM * SST;  // [2][BN][SST]

    const int tid = threadIdx.x;
    const int lane = tid & 31;
    const int wid = tid >> 5;
    const int warp_row = (wid & 1) * 64;
    const int warp_col = (wid >> 1) * 32;
    const int bm = blockIdx.y * BM;
    const int bn = blockIdx.x * BN;

    const int lc = (tid & 7) * 4;   // col within BK
    const int lr = tid >> 3;        // row base (32 rows per iter)

    const float* Xp = X + (size_t)bm * ldx;
    const float* Wp = W + (size_t)bn * K;

    float acc[4][4][4];
#pragma unroll
    for (int mi = 0; mi < 4; mi++)
#pragma unroll
        for (int ni = 0; ni < 4; ni++)
#pragma unroll
            for (int j = 0; j < 4; j++) acc[mi][ni][j] = 0.f;

    float4 ra[4], rb[4];

    // fetch k0 tile into regs
#define FETCH(k0)                                                              \
    {                                                                          \
        _Pragma("unroll") for (int it = 0; it < 4; it++) {                     \
            int r = lr + it * 32;                                              \
            ra[it] = *reinterpret_cast<const float4*>(Xp + (size_t)r * ldx + (k0) + lc); \
            rb[it] = *reinterpret_cast<const float4*>(Wp + (size_t)r * K + (k0) + lc);   \
        }                                                                      \
    }

#define STORE(sg)                                                              \
    {                                                                          \
        _Pragma("unroll") for (int it = 0; it < 4; it++) {                     \
            int r = lr + it * 32;                                              \
            uint4 at = {f2tf32(ra[it].x), f2tf32(ra[it].y),                    \
                        f2tf32(ra[it].z), f2tf32(ra[it].w)};                   \
            *reinterpret_cast<uint4*>(As + (sg)*BM*SST + r*SST + lc) = at;     \
            uint4 bt = {f2tf32(rb[it].x), f2tf32(rb[it].y),                    \
                        f2tf32(rb[it].z), f2tf32(rb[it].w)};                   \
            *reinterpret_cast<uint4*>(Bs + (sg)*BN*SST + r*SST + lc) = bt;     \
        }                                                                      \
    }

    FETCH(0);
    STORE(0);
    __syncthreads();

    const int g = lane >> 2;   // groupID
    const int q = lane & 3;

    for (int k0 = 0; k0 < K; k0 += BK) {
        const int s = (k0 / BK) & 1;
        const bool more = (k0 + BK) < K;
        if (more) FETCH(k0 + BK);

        const uint32_t* Ab = As + s * BM * SST;
        const uint32_t* Bb = Bs + s * BN * SST;
#pragma unroll
        for (int kk = 0; kk < 4; kk++) {
            uint32_t af[4][4], bf[4][2];
            const int kc = kk * 8 + q;
#pragma unroll
            for (int mi = 0; mi < 4; mi++) {
                const uint32_t* p = Ab + (warp_row + mi * 16 + g) * SST + kc;
                af[mi][0] = p[0];
                af[mi][1] = p[8 * SST];
                af[mi][2] = p[4];
                af[mi][3] = p[8 * SST + 4];
            }
#pragma unroll
            for (int ni = 0; ni < 4; ni++) {
                const uint32_t* p = Bb + (warp_col + ni * 8 + g) * SST + kc;
                bf[ni][0] = p[0];
                bf[ni][1] = p[4];
            }
#pragma unroll
            for (int mi = 0; mi < 4; mi++)
#pragma unroll
                for (int ni = 0; ni < 4; ni++)
                    mma_tf32(acc[mi][ni], af[mi], bf[ni][0], bf[ni][1]);
        }
        if (more) STORE(s ^ 1);
        __syncthreads();
    }

    // epilogue
#pragma unroll
    for (int mi = 0; mi < 4; mi++) {
        const int row0 = bm + warp_row + mi * 16 + g;
#pragma unroll
        for (int ni = 0; ni < 4; ni++) {
            const int col = bn + warp_col + ni * 8 + 2 * q;
            float2 bb = *reinterpret_cast<const float2*>(bias + col);
            float v0 = acc[mi][ni][0] + bb.x;
            float v1 = acc[mi][ni][1] + bb.y;
            float v2 = acc[mi][ni][2] + bb.x;
            float v3 = acc[mi][ni][3] + bb.y;
            if (addend) {
                float2 a0 = *reinterpret_cast<const float2*>(addend + (size_t)row0 * N + col);
                float2 a1 = *reinterpret_cast<const float2*>(addend + (size_t)(row0 + 8) * N + col);
                v0 += a0.x; v1 += a0.y; v2 += a1.x; v3 += a1.y;
            }
            *reinterpret_cast<float2*>(Y + (size_t)row0 * N + col) = make_float2(v0, v1);
            *reinterpret_cast<float2*>(Y + (size_t)(row0 + 8) * N + col) = make_float2(v2, v3);
        }
    }
#undef FETCH
#undef STORE
}

// ---------------- tensor-core flash attention -------------------------------
// 4 warps, 64 queries x one head per CTA; Q frags in regs; Q smem reused as P.
#define AST 68   // smem row stride (floats)

__global__ void __launch_bounds__(128) attn_tc(
    const float* __restrict__ qkv, float* __restrict__ out, int L)
{
    extern __shared__ uint32_t sm[];
    uint32_t* Qs = sm;                  // [64][AST]  (later reused as P)
    uint32_t* Ks = sm + 64 * AST;
    uint32_t* Vs = sm + 2 * 64 * AST;
    uint32_t* Ps = Qs;

    const int h = blockIdx.y;
    const int q0 = blockIdx.x * 64;
    const int tid = threadIdx.x;
    const int wid = tid >> 5;
    const int lane = tid & 31;
    const int g = lane >> 2;
    const int q = lane & 3;

    const int lc = (tid & 15) * 4;  // col group
    const int lr0 = tid >> 4;       // row base, 8 rows/iter

    // load Q (pre-scaled by 1/sqrt(64)) as tf32
#pragma unroll
    for (int it = 0; it < 8; it++) {
        int r = lr0 + it * 8;
        float4 v = *reinterpret_cast<const float4*>(
            qkv + (size_t)(q0 + r) * 3072 + h * 64 + lc);
        uint4 t = {f2tf32(v.x * 0.125f), f2tf32(v.y * 0.125f),
                   f2tf32(v.z * 0.125f), f2tf32(v.w * 0.125f)};
        *reinterpret_cast<uint4*>(Qs + r * AST + lc) = t;
    }
    __syncthreads();

    // preload Q fragments (8 k-steps), then Qs is free for P (warp-local rows)
    uint32_t qa[8][4];
    const int arow = wid * 16 + g;
#pragma unroll
    for (int kk = 0; kk < 8; kk++) {
        const uint32_t* p = Qs + arow * AST + kk * 8 + q;
        qa[kk][0] = p[0];
        qa[kk][1] = p[8 * AST];
        qa[kk][2] = p[4];
        qa[kk][3] = p[8 * AST + 4];
    }

    float m_i[2] = {-1e30f, -1e30f};
    float l_i[2] = {0.f, 0.f};
    float O[8][4];
#pragma unroll
    for (int ni = 0; ni < 8; ni++)
#pragma unroll
        for (int j = 0; j < 4; j++) O[ni][j] = 0.f;

    for (int kb = 0; kb < L; kb += 64) {
        __syncthreads();  // prior block's K/V reads complete
#pragma unroll
        for (int it = 0; it < 8; it++) {
            int r = lr0 + it * 8;
            const float* base = qkv + (size_t)(kb + r) * 3072 + h * 64 + lc;
            float4 kv = *reinterpret_cast<const float4*>(base + 1024);
            uint4 kt = {f2tf32(kv.x), f2tf32(kv.y), f2tf32(kv.z), f2tf32(kv.w)};
            *reinterpret_cast<uint4*>(Ks + r * AST + lc) = kt;
            float4 vv = *reinterpret_cast<const float4*>(base + 2048);
            uint4 vt = {f2tf32(vv.x), f2tf32(vv.y), f2tf32(vv.z), f2tf32(vv.w)};
            *reinterpret_cast<uint4*>(Vs + r * AST + lc) = vt;
        }
        __syncthreads();

        // S = Q @ K^T
        float s[8][4];
#pragma unroll
        for (int ni = 0; ni < 8; ni++)
#pragma unroll
            for (int j = 0; j < 4; j++) s[ni][j] = 0.f;
#pragma unroll
        for (int kk = 0; kk < 8; kk++) {
            const int kc = kk * 8 + q;
#pragma unroll
            for (int ni = 0; ni < 8; ni++) {
                const uint32_t* p = Ks + (ni * 8 + g) * AST + kc;
                mma_tf32(s[ni], qa[kk], p[0], p[4]);
            }
        }

        // online softmax (rows: r = arow, r+8)
        float rmax0 = -1e30f, rmax1 = -1e30f;
#pragma unroll
        for (int ni = 0; ni < 8; ni++) {
            rmax0 = fmaxf(rmax0, fmaxf(s[ni][0], s[ni][1]));
            rmax1 = fmaxf(rmax1, fmaxf(s[ni][2], s[ni][3]));
        }
#pragma unroll
        for (int off = 1; off <= 2; off <<= 1) {
            rmax0 = fmaxf(rmax0, __shfl_xor_sync(0xffffffffu, rmax0, off));
            rmax1 = fmaxf(rmax1, __shfl_xor_sync(0xffffffffu, rmax1, off));
        }
        float mnew0 = fmaxf(m_i[0], rmax0);
        float mnew1 = fmaxf(m_i[1], rmax1);
        float al0 = __expf(m_i[0] - mnew0);
        float al1 = __expf(m_i[1] - mnew1);
        float sum0 = 0.f, sum1 = 0.f;
#pragma unroll
        for (int ni = 0; ni < 8; ni++) {
            s[ni][0] = __expf(s[ni][0] - mnew0);
            s[ni][1] = __expf(s[ni][1] - mnew0);
            s[ni][2] = __expf(s[ni][2] - mnew1);
            s[ni][3] = __expf(s[ni][3] - mnew1);
            sum0 += s[ni][0] + s[ni][1];
            sum1 += s[ni][2] + s[ni][3];
        }
#pragma unroll
        for (int off = 1; off <= 2; off <<= 1) {
            sum0 += __shfl_xor_sync(0xffffffffu, sum0, off);
            sum1 += __shfl_xor_sync(0xffffffffu, sum1, off);
        }
        l_i[0] = l_i[0] * al0 + sum0;
        l_i[1] = l_i[1] * al1 + sum1;
        m_i[0] = mnew0;
        m_i[1] = mnew1;
#pragma unroll
        for (int ni = 0; ni < 8; ni++) {
            O[ni][0] *= al0; O[ni][1] *= al0;
            O[ni][2] *= al1; O[ni][3] *= al1;
        }

        // write P (warp-local rows of reused Q region)
        __syncwarp();
#pragma unroll
        for (int ni = 0; ni < 8; ni++) {
            const int col = ni * 8 + 2 * q;
            Ps[arow * AST + col]           = f2tf32(s[ni][0]);
            Ps[arow * AST + col + 1]       = f2tf32(s[ni][1]);
            Ps[(arow + 8) * AST + col]     = f2tf32(s[ni][2]);
            Ps[(arow + 8) * AST + col + 1] = f2tf32(s[ni][3]);
        }
        __syncwarp();

        // O += P @ V
#pragma unroll
        for (int kk = 0; kk < 8; kk++) {
            uint32_t pa[4];
            const uint32_t* pp = Ps + arow * AST + kk * 8 + q;
            pa[0] = pp[0];
            pa[1] = pp[8 * AST];
            pa[2] = pp[4];
            pa[3] = pp[8 * AST + 4];
#pragma unroll
            for (int ni = 0; ni < 8; ni++) {
                const uint32_t* vp = Vs + (kk * 8 + q) * AST + ni * 8 + g;
                mma_tf32(O[ni], pa, vp[0], vp[4 * AST]);
            }
        }
    }

    // normalize + write
    const float inv0 = 1.0f / l_i[0];
    const float inv1 = 1.0f / l_i[1];
    const size_t row0 = (size_t)(q0 + arow);
#pragma unroll
    for (int ni = 0; ni < 8; ni++) {
        const int col = h * 64 + ni * 8 + 2 * q;
        *reinterpret_cast<float2*>(out + row0 * E_DIM + col) =
            make_float2(O[ni][0] * inv0, O[ni][1] * inv0);
        *reinterpret_cast<float2*>(out + (row0 + 8) * E_DIM + col) =
            make_float2(O[ni][2] * inv1, O[ni][3] * inv1);
    }
}

// ---------------- linear upsample -------------------------------------------
__global__ void __launch_bounds__(256) upsample_kernel(
    const float* __restrict__ x, float* __restrict__ y, int Lsrc, int Ltar)
{
    const int i = blockIdx.x;
    float src = (i + 0.5f) * ((float)Lsrc / (float)Ltar) - 0.5f;
    src = fminf(fmaxf(src, 0.f), (float)(Lsrc - 1));
    int i0 = (int)floorf(src);
    int i1 = min(i0 + 1, Lsrc - 1);
    float w = src - (float)i0;
    const float* a = x + (size_t)i0 * E_DIM;
    const float* b = x + (size_t)i1 * E_DIM;
    float* yp = y + (size_t)i * E_DIM;
    for (int c = threadIdx.x * 4; c < E_DIM; c += blockDim.x * 4) {
        float4 va = *reinterpret_cast<const float4*>(a + c);
        float4 vb = *reinterpret_cast<const float4*>(b + c);
        float4 r;
        r.x = va.x + (vb.x - va.x) * w;
        r.y = va.y + (vb.y - va.y) * w;
        r.z = va.z + (vb.z - va.z) * w;
        r.w = va.w + (vb.w - va.w) * w;
        *reinterpret_cast<float4*>(yp + c) = r;
    }
}

// ---------------- launcher --------------------------------------------------
extern "C" void kernel_launch(void* const* d_in, const int* in_sizes, int n_in,
                              void* d_out, int out_size)
{
    const float* query = (const float*)d_in[0];
    const float* in_w  = (const float*)d_in[1];
    const float* in_b  = (const float*)d_in[2];
    const float* out_w = (const float*)d_in[3];
    const float* out_b = (const float*)d_in[4];
    const float* up_w  = (const float*)d_in[5];
    const float* up_b  = (const float*)d_in[6];
    float* out = (float*)d_out;

    const int GEMM_SMEM = 2 * 2 * BM * SST * 4;   // 73728 B
    const int ATTN_SMEM = 3 * 64 * AST * 4;       // 52224 B
    cudaFuncSetAttribute(gemm_tc, cudaFuncAttributeMaxDynamicSharedMemorySize, GEMM_SMEM);
    cudaFuncSetAttribute(attn_tc, cudaFuncAttributeMaxDynamicSharedMemorySize, ATTN_SMEM);

    float *qkv, *attn, *outs, *ups, *cur;
    cudaGetSymbolAddress((void**)&qkv,  g_qkv);
    cudaGetSymbolAddress((void**)&attn, g_attn);
    cudaGetSymbolAddress((void**)&outs, g_outs);
    cudaGetSymbolAddress((void**)&ups,  g_ups);
    cudaGetSymbolAddress((void**)&cur,  g_cur);

    const size_t off[LEVELS] = {0, 2048u * E_DIM, 3072u * E_DIM, 3584u * E_DIM};

    for (int lvl = 0; lvl < LEVELS; lvl++) {
        const int L = S_MAX >> lvl;
        const int stride = 1 << lvl;

        gemm_tc<<<dim3(3 * E_DIM / BN, L / BM), 256, GEMM_SMEM>>>(
            query, stride * E_DIM,
            in_w + (size_t)lvl * 3 * E_DIM * E_DIM,
            in_b + (size_t)lvl * 3 * E_DIM,
            nullptr, qkv, L, 3 * E_DIM, E_DIM);

        attn_tc<<<dim3(L / 64, 16), 128, ATTN_SMEM>>>(qkv, attn, L);

        gemm_tc<<<dim3(E_DIM / BN, L / BM), 256, GEMM_SMEM>>>(
            attn, E_DIM,
            out_w + (size_t)lvl * E_DIM * E_DIM,
            out_b + (size_t)lvl * E_DIM,
            nullptr, outs + off[lvl], L, E_DIM, E_DIM);
    }

    const float* curp = outs + off[3];
    int Lc = 256;
    for (int lvl = LEVELS - 2; lvl >= 0; lvl--) {
        const int Lf = S_MAX >> lvl;
        upsample_kernel<<<Lf, 256>>>(curp, ups, Lc, Lf);
        float* dst = (lvl == 0) ? out : cur;
        gemm_tc<<<dim3(E_DIM / BN, Lf / BM), 256, GEMM_SMEM>>>(
            ups, E_DIM,
            up_w + (size_t)lvl * E_DIM * E_DIM,
            up_b + (size_t)lvl * E_DIM,
            outs + off[lvl],
            dst, Lf, E_DIM, E_DIM);
        curp = dst;
        Lc = Lf;
    }
}

// round 4
// speedup vs baseline: 3.7564x; 1.2221x over previous
#include <cuda_runtime.h>
#include <cstdint>

#define E_DIM 1024
#define S_MAX 2048
#define LEVELS 4
#define R_TOT 3840   // 2048+1024+512+256

// ---------------- scratch ---------------------------------------------------
__device__ float g_qkv[R_TOT * 3 * E_DIM];
__device__ float g_attn[R_TOT * E_DIM];
__device__ float g_outs[R_TOT * E_DIM];
__device__ float g_cur1[1024 * E_DIM];
__device__ float g_cur2[512 * E_DIM];

// ---------------- helpers ---------------------------------------------------
__device__ __forceinline__ uint32_t f2tf32(float f) {
    uint32_t r;
    asm("cvt.rna.tf32.f32 %0, %1;" : "=r"(r) : "f"(f));
    return r;
}

__device__ __forceinline__ void mma_tf32(float* c, const uint32_t* a,
                                         uint32_t b0, uint32_t b1) {
    asm volatile(
        "mma.sync.aligned.m16n8k8.row.col.f32.tf32.tf32.f32 "
        "{%0,%1,%2,%3}, {%4,%5,%6,%7}, {%8,%9}, {%0,%1,%2,%3};"
        : "+f"(c[0]), "+f"(c[1]), "+f"(c[2]), "+f"(c[3])
        : "r"(a[0]), "r"(a[1]), "r"(a[2]), "r"(a[3]), "r"(b0), "r"(b1));
}

// ---------------- shared GEMM core ------------------------------------------
// Y[M,N](level-local base) = A @ W[N,K]^T + bias (+addend); A via functor fa(row,col)->float4
#define BM 128
#define BN 128
#define BK 32
#define SST 36
#define GEMM_SMEM (2 * 2 * BM * SST * 4)

template <class FA>
__device__ __forceinline__ void gemm_core(
    FA fa,
    const float* __restrict__ Wp,       // W + bn*K
    const float* __restrict__ bias,     // full bias
    const float* __restrict__ addend,   // level base or nullptr
    float* __restrict__ Y,              // level base
    int N, int K, int bm, int bn,
    uint32_t* As, uint32_t* Bs)
{
    const int tid = threadIdx.x;
    const int lane = tid & 31;
    const int wid = tid >> 5;
    const int warp_row = (wid & 1) * 64;
    const int warp_col = (wid >> 1) * 32;

    const int lc = (tid & 7) * 4;
    const int lr = tid >> 3;

    float acc[4][4][4];
#pragma unroll
    for (int mi = 0; mi < 4; mi++)
#pragma unroll
        for (int ni = 0; ni < 4; ni++)
#pragma unroll
            for (int j = 0; j < 4; j++) acc[mi][ni][j] = 0.f;

    float4 ra[4], rb[4];

#define G_FETCH(k0)                                                            \
    {                                                                          \
        _Pragma("unroll") for (int it = 0; it < 4; it++) {                     \
            int r = lr + it * 32;                                              \
            ra[it] = fa(bm + r, (k0) + lc);                                    \
            rb[it] = *reinterpret_cast<const float4*>(Wp + (size_t)r * K + (k0) + lc); \
        }                                                                      \
    }

#define G_STORE(sg)                                                            \
    {                                                                          \
        _Pragma("unroll") for (int it = 0; it < 4; it++) {                     \
            int r = lr + it * 32;                                              \
            uint4 at = {f2tf32(ra[it].x), f2tf32(ra[it].y),                    \
                        f2tf32(ra[it].z), f2tf32(ra[it].w)};                   \
            *reinterpret_cast<uint4*>(As + (sg)*BM*SST + r*SST + lc) = at;     \
            uint4 bt = {f2tf32(rb[it].x), f2tf32(rb[it].y),                    \
                        f2tf32(rb[it].z), f2tf32(rb[it].w)};                   \
            *reinterpret_cast<uint4*>(Bs + (sg)*BN*SST + r*SST + lc) = bt;     \
        }                                                                      \
    }

    G_FETCH(0);
    G_STORE(0);
    __syncthreads();

    const int g = lane >> 2;
    const int q = lane & 3;

    for (int k0 = 0; k0 < K; k0 += BK) {
        const int s = (k0 / BK) & 1;
        const bool more = (k0 + BK) < K;
        if (more) G_FETCH(k0 + BK);

        const uint32_t* Ab = As + s * BM * SST;
        const uint32_t* Bb = Bs + s * BN * SST;
#pragma unroll
        for (int kk = 0; kk < 4; kk++) {
            uint32_t af[4][4], bf[4][2];
            const int kc = kk * 8 + q;
#pragma unroll
            for (int mi = 0; mi < 4; mi++) {
                const uint32_t* p = Ab + (warp_row + mi * 16 + g) * SST + kc;
                af[mi][0] = p[0];
                af[mi][1] = p[8 * SST];
                af[mi][2] = p[4];
                af[mi][3] = p[8 * SST + 4];
            }
#pragma unroll
            for (int ni = 0; ni < 4; ni++) {
                const uint32_t* p = Bb + (warp_col + ni * 8 + g) * SST + kc;
                bf[ni][0] = p[0];
                bf[ni][1] = p[4];
            }
#pragma unroll
            for (int mi = 0; mi < 4; mi++)
#pragma unroll
                for (int ni = 0; ni < 4; ni++)
                    mma_tf32(acc[mi][ni], af[mi], bf[ni][0], bf[ni][1]);
        }
        if (more) G_STORE(s ^ 1);
        __syncthreads();
    }

#pragma unroll
    for (int mi = 0; mi < 4; mi++) {
        const int row0 = bm + warp_row + mi * 16 + g;
#pragma unroll
        for (int ni = 0; ni < 4; ni++) {
            const int col = bn + warp_col + ni * 8 + 2 * q;
            float2 bb = *reinterpret_cast<const float2*>(bias + col);
            float v0 = acc[mi][ni][0] + bb.x;
            float v1 = acc[mi][ni][1] + bb.y;
            float v2 = acc[mi][ni][2] + bb.x;
            float v3 = acc[mi][ni][3] + bb.y;
            if (addend) {
                float2 a0 = *reinterpret_cast<const float2*>(addend + (size_t)row0 * N + col);
                float2 a1 = *reinterpret_cast<const float2*>(addend + (size_t)(row0 + 8) * N + col);
                v0 += a0.x; v1 += a0.y; v2 += a1.x; v3 += a1.y;
            }
            *reinterpret_cast<float2*>(Y + (size_t)row0 * N + col) = make_float2(v0, v1);
            *reinterpret_cast<float2*>(Y + (size_t)(row0 + 8) * N + col) = make_float2(v2, v3);
        }
    }
#undef G_FETCH
#undef G_STORE
}

// A-load functors
struct PlainFA {
    const float* X; int ldx;
    __device__ __forceinline__ float4 operator()(int r, int c) const {
        return *reinterpret_cast<const float4*>(X + (size_t)r * ldx + c);
    }
};
struct UpFA {   // linear 2x upsample of src[Lsrc] rows
    const float* src; int Lsrc;
    __device__ __forceinline__ float4 operator()(int r, int c) const {
        float s = 0.5f * (float)r - 0.25f;
        s = fminf(fmaxf(s, 0.f), (float)(Lsrc - 1));
        int i0 = (int)floorf(s);
        int i1 = min(i0 + 1, Lsrc - 1);
        float w = s - (float)i0;
        float4 a = *reinterpret_cast<const float4*>(src + (size_t)i0 * E_DIM + c);
        float4 b = *reinterpret_cast<const float4*>(src + (size_t)i1 * E_DIM + c);
        float4 o;
        o.x = a.x + (b.x - a.x) * w;
        o.y = a.y + (b.y - a.y) * w;
        o.z = a.z + (b.z - a.z) * w;
        o.w = a.w + (b.w - a.w) * w;
        return o;
    }
};

// level tables (device-side constants)
__device__ __constant__ int d_qoff[4] = {0, 2048, 3072, 3584};
__device__ __constant__ int d_rbCum[5] = {0, 16, 24, 28, 30};   // row blocks /128
__device__ __constant__ int d_qbCum[5] = {0, 32, 48, 56, 60};   // q blocks /64
__device__ __constant__ int d_Llvl[4] = {2048, 1024, 512, 256};

// ---------------- batched QKV projection ------------------------------------
__global__ void __launch_bounds__(256) gemm_qkv_all(
    const float* __restrict__ query,
    const float* __restrict__ in_w,
    const float* __restrict__ in_b)
{
    extern __shared__ uint32_t smem[];
    const int by = blockIdx.y;
    int lvl = 0;
#pragma unroll
    for (int i = 0; i < 3; i++) if (by >= d_rbCum[i + 1]) lvl = i + 1;
    const int bm = (by - d_rbCum[lvl]) * BM;
    const int bn = blockIdx.x * BN;
    const int stride = 1 << lvl;

    PlainFA fa{query, stride * E_DIM};
    gemm_core(fa,
              in_w + (size_t)lvl * 3 * E_DIM * E_DIM + (size_t)bn * E_DIM,
              in_b + (size_t)lvl * 3 * E_DIM,
              nullptr,
              g_qkv + (size_t)d_qoff[lvl] * 3 * E_DIM,
              3 * E_DIM, E_DIM, bm, bn,
              smem, smem + 2 * BM * SST);
}

// ---------------- batched out projection ------------------------------------
__global__ void __launch_bounds__(256) gemm_out_all(
    const float* __restrict__ out_w,
    const float* __restrict__ out_b)
{
    extern __shared__ uint32_t smem[];
    const int by = blockIdx.y;
    int lvl = 0;
#pragma unroll
    for (int i = 0; i < 3; i++) if (by >= d_rbCum[i + 1]) lvl = i + 1;
    const int bm = (by - d_rbCum[lvl]) * BM;
    const int bn = blockIdx.x * BN;

    PlainFA fa{g_attn + (size_t)d_qoff[lvl] * E_DIM, E_DIM};
    gemm_core(fa,
              out_w + (size_t)lvl * E_DIM * E_DIM + (size_t)bn * E_DIM,
              out_b + (size_t)lvl * E_DIM,
              nullptr,
              g_outs + (size_t)d_qoff[lvl] * E_DIM,
              E_DIM, E_DIM, bm, bn,
              smem, smem + 2 * BM * SST);
}

// ---------------- combine: fused upsample + projection + residual -----------
__global__ void __launch_bounds__(256) gemm_up(
    const float* __restrict__ src, int Lsrc,
    const float* __restrict__ W,
    const float* __restrict__ bias,
    const float* __restrict__ addend,
    float* __restrict__ Y)
{
    extern __shared__ uint32_t smem[];
    UpFA fa{src, Lsrc};
    gemm_core(fa,
              W + (size_t)blockIdx.x * BN * E_DIM,
              bias, addend, Y,
              E_DIM, E_DIM, blockIdx.y * BM, blockIdx.x * BN,
              smem, smem + 2 * BM * SST);
}

// ---------------- batched tensor-core flash attention -----------------------
#define AST 68
#define ATTN_SMEM (3 * 64 * AST * 4)

__global__ void __launch_bounds__(128) attn_all()
{
    extern __shared__ uint32_t sm[];
    uint32_t* Qs = sm;
    uint32_t* Ks = sm + 64 * AST;
    uint32_t* Vs = sm + 2 * 64 * AST;
    uint32_t* Ps = Qs;

    const int bx = blockIdx.x;
    int lvl = 0;
#pragma unroll
    for (int i = 0; i < 3; i++) if (bx >= d_qbCum[i + 1]) lvl = i + 1;
    const int L = d_Llvl[lvl];
    const float* qkv = g_qkv + (size_t)d_qoff[lvl] * 3 * E_DIM;
    float* out = g_attn + (size_t)d_qoff[lvl] * E_DIM;

    const int h = blockIdx.y;
    const int q0 = (bx - d_qbCum[lvl]) * 64;
    const int tid = threadIdx.x;
    const int wid = tid >> 5;
    const int lane = tid & 31;
    const int g = lane >> 2;
    const int q = lane & 3;

    const int lc = (tid & 15) * 4;
    const int lr0 = tid >> 4;

#pragma unroll
    for (int it = 0; it < 8; it++) {
        int r = lr0 + it * 8;
        float4 v = *reinterpret_cast<const float4*>(
            qkv + (size_t)(q0 + r) * 3072 + h * 64 + lc);
        uint4 t = {f2tf32(v.x * 0.125f), f2tf32(v.y * 0.125f),
                   f2tf32(v.z * 0.125f), f2tf32(v.w * 0.125f)};
        *reinterpret_cast<uint4*>(Qs + r * AST + lc) = t;
    }
    __syncthreads();

    uint32_t qa[8][4];
    const int arow = wid * 16 + g;
#pragma unroll
    for (int kk = 0; kk < 8; kk++) {
        const uint32_t* p = Qs + arow * AST + kk * 8 + q;
        qa[kk][0] = p[0];
        qa[kk][1] = p[8 * AST];
        qa[kk][2] = p[4];
        qa[kk][3] = p[8 * AST + 4];
    }

    float m_i[2] = {-1e30f, -1e30f};
    float l_i[2] = {0.f, 0.f};
    float O[8][4];
#pragma unroll
    for (int ni = 0; ni < 8; ni++)
#pragma unroll
        for (int j = 0; j < 4; j++) O[ni][j] = 0.f;

    for (int kb = 0; kb < L; kb += 64) {
        __syncthreads();
#pragma unroll
        for (int it = 0; it < 8; it++) {
            int r = lr0 + it * 8;
            const float* base = qkv + (size_t)(kb + r) * 3072 + h * 64 + lc;
            float4 kv = *reinterpret_cast<const float4*>(base + 1024);
            uint4 kt = {f2tf32(kv.x), f2tf32(kv.y), f2tf32(kv.z), f2tf32(kv.w)};
            *reinterpret_cast<uint4*>(Ks + r * AST + lc) = kt;
            float4 vv = *reinterpret_cast<const float4*>(base + 2048);
            uint4 vt = {f2tf32(vv.x), f2tf32(vv.y), f2tf32(vv.z), f2tf32(vv.w)};
            *reinterpret_cast<uint4*>(Vs + r * AST + lc) = vt;
        }
        __syncthreads();

        float s[8][4];
#pragma unroll
        for (int ni = 0; ni < 8; ni++)
#pragma unroll
            for (int j = 0; j < 4; j++) s[ni][j] = 0.f;
#pragma unroll
        for (int kk = 0; kk < 8; kk++) {
            const int kc = kk * 8 + q;
#pragma unroll
            for (int ni = 0; ni < 8; ni++) {
                const uint32_t* p = Ks + (ni * 8 + g) * AST + kc;
                mma_tf32(s[ni], qa[kk], p[0], p[4]);
            }
        }

        float rmax0 = -1e30f, rmax1 = -1e30f;
#pragma unroll
        for (int ni = 0; ni < 8; ni++) {
            rmax0 = fmaxf(rmax0, fmaxf(s[ni][0], s[ni][1]));
            rmax1 = fmaxf(rmax1, fmaxf(s[ni][2], s[ni][3]));
        }
#pragma unroll
        for (int off = 1; off <= 2; off <<= 1) {
            rmax0 = fmaxf(rmax0, __shfl_xor_sync(0xffffffffu, rmax0, off));
            rmax1 = fmaxf(rmax1, __shfl_xor_sync(0xffffffffu, rmax1, off));
        }
        float mnew0 = fmaxf(m_i[0], rmax0);
        float mnew1 = fmaxf(m_i[1], rmax1);
        float al0 = __expf(m_i[0] - mnew0);
        float al1 = __expf(m_i[1] - mnew1);
        float sum0 = 0.f, sum1 = 0.f;
#pragma unroll
        for (int ni = 0; ni < 8; ni++) {
            s[ni][0] = __expf(s[ni][0] - mnew0);
            s[ni][1] = __expf(s[ni][1] - mnew0);
            s[ni][2] = __expf(s[ni][2] - mnew1);
            s[ni][3] = __expf(s[ni][3] - mnew1);
            sum0 += s[ni][0] + s[ni][1];
            sum1 += s[ni][2] + s[ni][3];
        }
#pragma unroll
        for (int off = 1; off <= 2; off <<= 1) {
            sum0 += __shfl_xor_sync(0xffffffffu, sum0, off);
            sum1 += __shfl_xor_sync(0xffffffffu, sum1, off);
        }
        l_i[0] = l_i[0] * al0 + sum0;
        l_i[1] = l_i[1] * al1 + sum1;
        m_i[0] = mnew0;
        m_i[1] = mnew1;
#pragma unroll
        for (int ni = 0; ni < 8; ni++) {
            O[ni][0] *= al0; O[ni][1] *= al0;
            O[ni][2] *= al1; O[ni][3] *= al1;
        }

        __syncwarp();
#pragma unroll
        for (int ni = 0; ni < 8; ni++) {
            const int col = ni * 8 + 2 * q;
            Ps[arow * AST + col]           = f2tf32(s[ni][0]);
            Ps[arow * AST + col + 1]       = f2tf32(s[ni][1]);
            Ps[(arow + 8) * AST + col]     = f2tf32(s[ni][2]);
            Ps[(arow + 8) * AST + col + 1] = f2tf32(s[ni][3]);
        }
        __syncwarp();

#pragma unroll
        for (int kk = 0; kk < 8; kk++) {
            uint32_t pa[4];
            const uint32_t* pp = Ps + arow * AST + kk * 8 + q;
            pa[0] = pp[0];
            pa[1] = pp[8 * AST];
            pa[2] = pp[4];
            pa[3] = pp[8 * AST + 4];
#pragma unroll
            for (int ni = 0; ni < 8; ni++) {
                const uint32_t* vp = Vs + (kk * 8 + q) * AST + ni * 8 + g;
                mma_tf32(O[ni], pa, vp[0], vp[4 * AST]);
            }
        }
    }

    const float inv0 = 1.0f / l_i[0];
    const float inv1 = 1.0f / l_i[1];
    const size_t row0 = (size_t)(q0 + arow);
#pragma unroll
    for (int ni = 0; ni < 8; ni++) {
        const int col = h * 64 + ni * 8 + 2 * q;
        *reinterpret_cast<float2*>(out + row0 * E_DIM + col) =
            make_float2(O[ni][0] * inv0, O[ni][1] * inv0);
        *reinterpret_cast<float2*>(out + (row0 + 8) * E_DIM + col) =
            make_float2(O[ni][2] * inv1, O[ni][3] * inv1);
    }
}

// ---------------- launcher --------------------------------------------------
extern "C" void kernel_launch(void* const* d_in, const int* in_sizes, int n_in,
                              void* d_out, int out_size)
{
    const float* query = (const float*)d_in[0];
    const float* in_w  = (const float*)d_in[1];
    const float* in_b  = (const float*)d_in[2];
    const float* out_w = (const float*)d_in[3];
    const float* out_b = (const float*)d_in[4];
    const float* up_w  = (const float*)d_in[5];
    const float* up_b  = (const float*)d_in[6];
    float* out = (float*)d_out;

    cudaFuncSetAttribute(gemm_qkv_all, cudaFuncAttributeMaxDynamicSharedMemorySize, GEMM_SMEM);
    cudaFuncSetAttribute(gemm_out_all, cudaFuncAttributeMaxDynamicSharedMemorySize, GEMM_SMEM);
    cudaFuncSetAttribute(gemm_up,      cudaFuncAttributeMaxDynamicSharedMemorySize, GEMM_SMEM);
    cudaFuncSetAttribute(attn_all,     cudaFuncAttributeMaxDynamicSharedMemorySize, ATTN_SMEM);

    float *outs, *cur1, *cur2;
    cudaGetSymbolAddress((void**)&outs, g_outs);
    cudaGetSymbolAddress((void**)&cur1, g_cur1);
    cudaGetSymbolAddress((void**)&cur2, g_cur2);

    // all levels, one launch each
    gemm_qkv_all<<<dim3(3 * E_DIM / BN, 30), 256, GEMM_SMEM>>>(query, in_w, in_b);
    attn_all<<<dim3(60, 16), 128, ATTN_SMEM>>>();
    gemm_out_all<<<dim3(E_DIM / BN, 30), 256, GEMM_SMEM>>>(out_w, out_b);

    // top-down combine (fused upsample + proj + residual)
    const size_t off1 = 2048u * E_DIM, off2 = 3072u * E_DIM, off3 = 3584u * E_DIM;
    // lvl2: 256 -> 512
    gemm_up<<<dim3(E_DIM / BN, 512 / BM), 256, GEMM_SMEM>>>(
        outs + off3, 256, up_w + 2u * E_DIM * E_DIM, up_b + 2u * E_DIM,
        outs + off2, cur2);
    // lvl1: 512 -> 1024
    gemm_up<<<dim3(E_DIM / BN, 1024 / BM), 256, GEMM_SMEM>>>(
        cur2, 512, up_w + 1u * E_DIM * E_DIM, up_b + 1u * E_DIM,
        outs + off1, cur1);
    // lvl0: 1024 -> 2048
    gemm_up<<<dim3(E_DIM / BN, 2048 / BM), 256, GEMM_SMEM>>>(
        cur1, 1024, up_w, up_b,
        outs, out);
}